// round 14
// baseline (speedup 1.0000x reference)
#include <cuda_runtime.h>
#include <cuda_bf16.h>
#include <cstdint>

// Per-edge dot product: score[e] = dot(h[src[e]], h[dst[e]]), D=64.
//
// 4-lanes-per-edge, 16 edges per warp in 2 batches with L1 prefetch:
//  - lane sub (0..3) of group grp loads 32B chunks #sub and #(sub+4) of each
//    256B row via LDG.256; one instr covers half of 8 rows.
//  - batch B's 4 row-halves are prefetched to L1 (prefetch.global.L1, no
//    registers held) BEFORE batch A's loads -> warp MLP 4 -> 8 outstanding
//    L2 requests at unchanged register count / occupancy.
//  - 2-stage butterfly (8 edges per SHFL), contiguous 8-float stores.

#define ROWF 64  // floats per row

struct f8 { float v0, v1, v2, v3, v4, v5, v6, v7; };

__device__ __forceinline__ f8 ldg256(const float* p) {
    f8 r;
    asm volatile("ld.global.nc.v8.f32 {%0,%1,%2,%3,%4,%5,%6,%7}, [%8];"
                 : "=f"(r.v0), "=f"(r.v1), "=f"(r.v2), "=f"(r.v3),
                   "=f"(r.v4), "=f"(r.v5), "=f"(r.v6), "=f"(r.v7)
                 : "l"(p));
    return r;
}

__device__ __forceinline__ void prefetchL1(const float* p) {
    asm volatile("prefetch.global.L1 [%0];" :: "l"(p));
}

__device__ __forceinline__ float dot8(const f8& a, const f8& b) {
    float s0 = a.v0 * b.v0 + a.v1 * b.v1;
    float s1 = a.v2 * b.v2 + a.v3 * b.v3;
    float s2 = a.v4 * b.v4 + a.v5 * b.v5;
    float s3 = a.v6 * b.v6 + a.v7 * b.v7;
    return (s0 + s1) + (s2 + s3);
}

__global__ __launch_bounds__(256)
void u_dot_v_kernel(const float* __restrict__ h,
                    const int* __restrict__ src,
                    const int* __restrict__ dst,
                    float* __restrict__ out,
                    int n_edges)
{
    const int warp = threadIdx.x >> 5;
    const int lane = threadIdx.x & 31;
    const int grp  = lane >> 2;            // edge group within warp (0..7)
    const unsigned sub = lane & 3;         // lane within group
    const unsigned gmask = 0xFu << (grp << 2);

    // 16 edges per warp: batch A = e_base+grp, batch B = e_base+8+grp
    const int e_base = (blockIdx.x * 8 + warp) * 16;
    if (e_base >= n_edges) return;

    if (e_base + 15 < n_edges) {
        // ---- fast path ----
        const int eA = e_base + grp;
        const int eB = eA + 8;

        const unsigned sA = (unsigned)src[eA];
        const unsigned dA = (unsigned)dst[eA];
        const unsigned sB = (unsigned)src[eB];
        const unsigned dB = (unsigned)dst[eB];

        const float* psA = h + (size_t)sA * ROWF + sub * 8;
        const float* pdA = h + (size_t)dA * ROWF + sub * 8;
        const float* psB = h + (size_t)sB * ROWF + sub * 8;
        const float* pdB = h + (size_t)dB * ROWF + sub * 8;

        // prefetch batch B rows to L1 (no registers held)
        prefetchL1(psB);
        prefetchL1(psB + 32);
        prefetchL1(pdB);
        prefetchL1(pdB + 32);

        // batch A: 4 LDG.256 in flight
        const f8 a0 = ldg256(psA);
        const f8 a1 = ldg256(psA + 32);
        const f8 b0 = ldg256(pdA);
        const f8 b1 = ldg256(pdA + 32);

        float vA = dot8(a0, b0) + dot8(a1, b1);
        vA += __shfl_xor_sync(gmask, vA, 2);
        vA += __shfl_xor_sync(gmask, vA, 1);
        if (sub == 0) out[eA] = vA;

        // batch B: should be L1 hits by now
        const f8 c0 = ldg256(psB);
        const f8 c1 = ldg256(psB + 32);
        const f8 d0 = ldg256(pdB);
        const f8 d1 = ldg256(pdB + 32);

        float vB = dot8(c0, d0) + dot8(c1, d1);
        vB += __shfl_xor_sync(gmask, vB, 2);
        vB += __shfl_xor_sync(gmask, vB, 1);
        if (sub == 0) out[eB] = vB;
    } else {
        // ---- tail path: clamp indices, guard stores ----
        const int nm1 = n_edges - 1;
        for (int half = 0; half < 2; half++) {
            const int e = e_base + half * 8 + grp;
            const int ec = e <= nm1 ? e : nm1;

            const unsigned s = (unsigned)src[ec];
            const unsigned d = (unsigned)dst[ec];

            const float* ps = h + (size_t)s * ROWF + sub * 8;
            const float* pd = h + (size_t)d * ROWF + sub * 8;

            const f8 a0 = ldg256(ps);
            const f8 a1 = ldg256(ps + 32);
            const f8 b0 = ldg256(pd);
            const f8 b1 = ldg256(pd + 32);

            float v = dot8(a0, b0) + dot8(a1, b1);
            v += __shfl_xor_sync(gmask, v, 2);
            v += __shfl_xor_sync(gmask, v, 1);

            if (sub == 0 && e < n_edges) out[e] = v;
        }
    }
}

extern "C" void kernel_launch(void* const* d_in, const int* in_sizes, int n_in,
                              void* d_out, int out_size)
{
    const float* h   = (const float*)d_in[0];
    const int*   src = (const int*)d_in[1];
    const int*   dst = (const int*)d_in[2];
    float*       out = (float*)d_out;

    const int n_edges = in_sizes[1];
    const int edges_per_block = 8 * 16;  // 8 warps x 16 edges
    const int blocks = (n_edges + edges_per_block - 1) / edges_per_block;

    u_dot_v_kernel<<<blocks, 256>>>(h, src, dst, out, n_edges);
}

// round 15
// speedup vs baseline: 1.0056x; 1.0056x over previous
#include <cuda_runtime.h>
#include <cuda_bf16.h>
#include <cstdint>

// Per-edge dot product: score[e] = dot(h[src[e]], h[dst[e]]), D=64.
//
// R12 core (4-lanes-per-edge, 8 edges/warp, LDG.256 gathers, 2-stage
// butterfly) wrapped in a persistent grid-stride loop with next-iteration
// INDEX preload only (2 scalar regs; row data never held across iterations,
// unroll 1 to prevent register-bloating software pipelining).

#define ROWF 64  // floats per row

struct f8 { float v0, v1, v2, v3, v4, v5, v6, v7; };

__device__ __forceinline__ f8 ldg256(const float* p) {
    f8 r;
    asm volatile("ld.global.nc.v8.f32 {%0,%1,%2,%3,%4,%5,%6,%7}, [%8];"
                 : "=f"(r.v0), "=f"(r.v1), "=f"(r.v2), "=f"(r.v3),
                   "=f"(r.v4), "=f"(r.v5), "=f"(r.v6), "=f"(r.v7)
                 : "l"(p));
    return r;
}

__device__ __forceinline__ float dot8(const f8& a, const f8& b) {
    float s0 = a.v0 * b.v0 + a.v1 * b.v1;
    float s1 = a.v2 * b.v2 + a.v3 * b.v3;
    float s2 = a.v4 * b.v4 + a.v5 * b.v5;
    float s3 = a.v6 * b.v6 + a.v7 * b.v7;
    return (s0 + s1) + (s2 + s3);
}

__global__ __launch_bounds__(256)
void u_dot_v_kernel(const float* __restrict__ h,
                    const int* __restrict__ src,
                    const int* __restrict__ dst,
                    float* __restrict__ out,
                    int n_edges)
{
    const int warp = threadIdx.x >> 5;
    const int lane = threadIdx.x & 31;
    const int grp  = lane >> 2;            // edge group within warp (0..7)
    const unsigned sub = lane & 3;         // lane within group
    const unsigned gmask = 0xFu << (grp << 2);

    const int wg     = blockIdx.x * 8 + warp;   // global warp id
    const int nwarps = gridDim.x * 8;
    const int stride = nwarps * 8;              // edges per sweep
    const int nm1    = n_edges - 1;

    int eb = wg * 8;                       // this warp's first chunk base
    if (eb >= n_edges) return;

    // preload indices for the first chunk (clamped)
    int e0 = eb + grp;
    unsigned s = (unsigned)src[e0 <= nm1 ? e0 : nm1];
    unsigned d = (unsigned)dst[e0 <= nm1 ? e0 : nm1];

    #pragma unroll 1
    for (; eb < n_edges; eb += stride) {
        const int e = eb + grp;

        // preload NEXT chunk's indices (clamped; always safe)
        const int enext = eb + stride + grp;
        const int enc = enext <= nm1 ? enext : nm1;
        const unsigned sn = (unsigned)src[enc];
        const unsigned dn = (unsigned)dst[enc];

        const float* ps = h + (size_t)s * ROWF + sub * 8;
        const float* pd = h + (size_t)d * ROWF + sub * 8;

        // 4 LDG.256 in flight; each covers half of 8 rows (1KB)
        const f8 a0 = ldg256(ps);
        const f8 a1 = ldg256(ps + 32);
        const f8 b0 = ldg256(pd);
        const f8 b1 = ldg256(pd + 32);

        float v = dot8(a0, b0) + dot8(a1, b1);

        // 2-stage butterfly within each 4-lane group (8 edges per instr)
        v += __shfl_xor_sync(gmask, v, 2);
        v += __shfl_xor_sync(gmask, v, 1);

        if (sub == 0 && e < n_edges) out[e] = v;

        s = sn; d = dn;
    }
}

extern "C" void kernel_launch(void* const* d_in, const int* in_sizes, int n_in,
                              void* d_out, int out_size)
{
    const float* h   = (const float*)d_in[0];
    const int*   src = (const int*)d_in[1];
    const int*   dst = (const int*)d_in[2];
    float*       out = (float*)d_out;

    const int n_edges = in_sizes[1];
    if (n_edges <= 0) return;

    // persistent-ish grid: ~4 blocks per SM (GB300: 152 SMs)
    int blocks = 152 * 4;
    const int max_useful = (n_edges + 8 * 8 - 1) / (8 * 8);
    if (blocks > max_useful) blocks = max_useful;

    u_dot_v_kernel<<<blocks, 256>>>(h, src, dst, out, n_edges);
}

// round 16
// speedup vs baseline: 1.0522x; 1.0464x over previous
#include <cuda_runtime.h>
#include <cuda_bf16.h>
#include <cstdint>

// Per-edge dot product: score[e] = dot(h[src[e]], h[dst[e]]), D=64.
//
// Persistent grid-stride version of the R12 core (4-lanes-per-edge,
// 8 edges/warp/iter, LDG.256 gathers, 2-stage butterfly) with
// next-iteration INDEX preload (2 scalar regs only, unroll 1).
// R14 retry with the grid-size bug fixed: 8 blocks/SM so the occupancy
// ceiling is 100% (R14 launched 4/SM -> 50% occ and regressed).

#define ROWF 64  // floats per row

struct f8 { float v0, v1, v2, v3, v4, v5, v6, v7; };

__device__ __forceinline__ f8 ldg256(const float* p) {
    f8 r;
    asm volatile("ld.global.nc.v8.f32 {%0,%1,%2,%3,%4,%5,%6,%7}, [%8];"
                 : "=f"(r.v0), "=f"(r.v1), "=f"(r.v2), "=f"(r.v3),
                   "=f"(r.v4), "=f"(r.v5), "=f"(r.v6), "=f"(r.v7)
                 : "l"(p));
    return r;
}

__device__ __forceinline__ float dot8(const f8& a, const f8& b) {
    float s0 = a.v0 * b.v0 + a.v1 * b.v1;
    float s1 = a.v2 * b.v2 + a.v3 * b.v3;
    float s2 = a.v4 * b.v4 + a.v5 * b.v5;
    float s3 = a.v6 * b.v6 + a.v7 * b.v7;
    return (s0 + s1) + (s2 + s3);
}

__global__ __launch_bounds__(256)
void u_dot_v_kernel(const float* __restrict__ h,
                    const int* __restrict__ src,
                    const int* __restrict__ dst,
                    float* __restrict__ out,
                    int n_edges)
{
    const int warp = threadIdx.x >> 5;
    const int lane = threadIdx.x & 31;
    const int grp  = lane >> 2;            // edge group within warp (0..7)
    const unsigned sub = lane & 3;         // lane within group
    const unsigned gmask = 0xFu << (grp << 2);

    const int wg     = blockIdx.x * 8 + warp;   // global warp id
    const int nwarps = gridDim.x * 8;
    const int stride = nwarps * 8;              // edges per sweep
    const int nm1    = n_edges - 1;

    int eb = wg * 8;                       // this warp's first chunk base
    if (eb >= n_edges) return;

    // preload indices for the first chunk (clamped)
    const int e0 = eb + grp;
    unsigned s = (unsigned)src[e0 <= nm1 ? e0 : nm1];
    unsigned d = (unsigned)dst[e0 <= nm1 ? e0 : nm1];

    #pragma unroll 1
    for (; eb < n_edges; eb += stride) {
        const int e = eb + grp;

        // preload NEXT chunk's indices (clamped; always safe)
        const int enext = eb + stride + grp;
        const int enc = enext <= nm1 ? enext : nm1;
        const unsigned sn = (unsigned)src[enc];
        const unsigned dn = (unsigned)dst[enc];

        const float* ps = h + (size_t)s * ROWF + sub * 8;
        const float* pd = h + (size_t)d * ROWF + sub * 8;

        // 4 LDG.256 in flight; each covers half of 8 rows (1KB)
        const f8 a0 = ldg256(ps);
        const f8 a1 = ldg256(ps + 32);
        const f8 b0 = ldg256(pd);
        const f8 b1 = ldg256(pd + 32);

        float v = dot8(a0, b0) + dot8(a1, b1);

        // 2-stage butterfly within each 4-lane group (8 edges per instr)
        v += __shfl_xor_sync(gmask, v, 2);
        v += __shfl_xor_sync(gmask, v, 1);

        if (sub == 0 && e < n_edges) out[e] = v;

        s = sn; d = dn;
    }
}

extern "C" void kernel_launch(void* const* d_in, const int* in_sizes, int n_in,
                              void* d_out, int out_size)
{
    const float* h   = (const float*)d_in[0];
    const int*   src = (const int*)d_in[1];
    const int*   dst = (const int*)d_in[2];
    float*       out = (float*)d_out;

    const int n_edges = in_sizes[1];
    if (n_edges <= 0) return;

    // 8 blocks/SM x 256 threads = 2048 threads/SM (full occupancy ceiling)
    int blocks = 152 * 8;
    const int max_useful = (n_edges + 8 * 8 - 1) / (8 * 8);
    if (blocks > max_useful) blocks = max_useful;

    u_dot_v_kernel<<<blocks, 256>>>(h, src, dst, out, n_edges);
}